// round 12
// baseline (speedup 1.0000x reference)
#include <cuda_runtime.h>
#include <cuda_bf16.h>
#include <cstdint>
#include <math.h>

#define NTOK 4096
#define DDIM 768
#define HDIM 1536
#define NE   6

// ---------------- device scratch ----------------
__device__ int   g_perm[NTOK];
__device__ int   g_gstart[NE + 1];
__device__ float g_alpha[NE];
__device__ float g_sumsq[NTOK];                              // per-token ||pre||^2
__device__ int   g_cnt[NE * (NTOK / 64)];                    // per (group, mtile) arrival counter
__device__ __nv_bfloat16 g_xg[(size_t)NTOK * DDIM];          // gathered x, perm order (bf16)
__device__ __nv_bfloat16 g_h [(size_t)NTOK * HDIM];          // relu hidden, perm order
__device__ __nv_bfloat16 g_W1b[(size_t)NE * DDIM * HDIM];    // bf16 W1, native [e][d][h]
__device__ __nv_bfloat16 g_W2b[(size_t)NE * HDIM * DDIM];    // bf16 W2, native [e][h][d]
__device__ float g_pre[(size_t)NTOK * DDIM];                 // x + alpha*r, token order

// ---------------- asm helpers ----------------
__device__ __forceinline__ void cp_async16(void* smem, const void* g, bool pred) {
    uint32_t s = (uint32_t)__cvta_generic_to_shared(smem);
    int sz = pred ? 16 : 0;   // src-size 0 -> 16B zero-fill
    asm volatile("cp.async.cg.shared.global [%0], [%1], 16, %2;\n" :: "r"(s), "l"(g), "r"(sz));
}
#define CP_COMMIT() asm volatile("cp.async.commit_group;\n" ::: "memory")
#define CP_WAIT1()  asm volatile("cp.async.wait_group 1;\n" ::: "memory")

__device__ __forceinline__ void ldsm_x4(uint32_t& r0, uint32_t& r1, uint32_t& r2, uint32_t& r3,
                                        uint32_t addr) {
    asm volatile("ldmatrix.sync.aligned.m8n8.x4.shared.b16 {%0,%1,%2,%3}, [%4];"
                 : "=r"(r0), "=r"(r1), "=r"(r2), "=r"(r3) : "r"(addr));
}
__device__ __forceinline__ void ldsm_x4_t(uint32_t& r0, uint32_t& r1, uint32_t& r2, uint32_t& r3,
                                          uint32_t addr) {
    asm volatile("ldmatrix.sync.aligned.m8n8.x4.trans.shared.b16 {%0,%1,%2,%3}, [%4];"
                 : "=r"(r0), "=r"(r1), "=r"(r2), "=r"(r3) : "r"(addr));
}

__device__ __forceinline__ void mma16816(float* c, const uint32_t* a, const uint32_t* b) {
    asm volatile(
        "mma.sync.aligned.m16n8k16.row.col.f32.bf16.bf16.f32 "
        "{%0,%1,%2,%3}, {%4,%5,%6,%7}, {%8,%9}, {%0,%1,%2,%3};\n"
        : "+f"(c[0]), "+f"(c[1]), "+f"(c[2]), "+f"(c[3])
        : "r"(a[0]), "r"(a[1]), "r"(a[2]), "r"(a[3]), "r"(b[0]), "r"(b[1]));
}

// ---------------- prep: sort tokens by group + zero fusion scratch ----------------
__global__ void prep_kernel(const int* __restrict__ ids,
                            const int* __restrict__ e2g,
                            const float* __restrict__ raw_alpha,
                            int T) {
    __shared__ int cnt[NE];
    __shared__ int cur[NE];
    __shared__ unsigned char gid_s[NTOK];
    int tid = threadIdx.x;
    if (tid < NE) cnt[tid] = 0;
    // zero per-replay fusion scratch
    for (int i = tid; i < NTOK; i += blockDim.x) g_sumsq[i] = 0.f;
    for (int i = tid; i < NE * (NTOK / 64); i += blockDim.x) g_cnt[i] = 0;
    __syncthreads();
    for (int i = tid; i < NTOK; i += blockDim.x) {
        int ty = ids[i];
        ty = ty < 0 ? 0 : (ty > T - 1 ? T - 1 : ty);
        int gd = e2g[ty];
        gid_s[i] = (unsigned char)gd;
        atomicAdd(&cnt[gd], 1);
    }
    __syncthreads();
    if (tid == 0) {
        int acc = 0;
        for (int e = 0; e < NE; e++) { g_gstart[e] = acc; cur[e] = acc; acc += cnt[e]; }
        g_gstart[NE] = acc;
    }
    __syncthreads();
    for (int i = tid; i < NTOK; i += blockDim.x) {
        int pos = atomicAdd(&cur[gid_s[i]], 1);
        g_perm[pos] = i;
    }
    if (tid < NE) g_alpha[tid] = 0.05f / (1.0f + expf(-raw_alpha[tid]));
}

// ---------------- streaming fp32 -> bf16 weight convert (16 elems/thread) ----------------
__global__ void convert_kernel(const float* __restrict__ in, int which) {
    __nv_bfloat16* out = which ? g_W2b : g_W1b;
    size_t i0 = ((size_t)blockIdx.x * 256 + threadIdx.x) * 16;
    #pragma unroll
    for (int h = 0; h < 2; h++) {
        float4 a = *reinterpret_cast<const float4*>(in + i0 + h * 8);
        float4 b = *reinterpret_cast<const float4*>(in + i0 + h * 8 + 4);
        __nv_bfloat162 h0 = __floats2bfloat162_rn(a.x, a.y);
        __nv_bfloat162 h1 = __floats2bfloat162_rn(a.z, a.w);
        __nv_bfloat162 h2 = __floats2bfloat162_rn(b.x, b.y);
        __nv_bfloat162 h3 = __floats2bfloat162_rn(b.z, b.w);
        uint4 o;
        o.x = *reinterpret_cast<uint32_t*>(&h0);
        o.y = *reinterpret_cast<uint32_t*>(&h1);
        o.z = *reinterpret_cast<uint32_t*>(&h2);
        o.w = *reinterpret_cast<uint32_t*>(&h3);
        *reinterpret_cast<uint4*>(out + i0 + h * 8) = o;
    }
}

// ---------------- gather: two independent float4 chunks per thread ----------------
__global__ void gather_kernel(const float* __restrict__ x) {
    int base = blockIdx.x * 256 + threadIdx.x;    // 1536 blocks -> 393216 threads
    #pragma unroll
    for (int i = 0; i < 2; i++) {
        int idx = base + i * 393216;
        int p = idx / 192, j = idx % 192;
        int t = g_perm[p];
        float4 v = *(reinterpret_cast<const float4*>(x + (size_t)t * DDIM) + j);
        __nv_bfloat162 h0 = __floats2bfloat162_rn(v.x, v.y);
        __nv_bfloat162 h1 = __floats2bfloat162_rn(v.z, v.w);
        uint2 o;
        o.x = *reinterpret_cast<uint32_t*>(&h0);
        o.y = *reinterpret_cast<uint32_t*>(&h1);
        *(reinterpret_cast<uint2*>(g_xg + (size_t)p * DDIM) + j) = o;
    }
}

// ---------------- grouped GEMM: BM=64, 3-stage cp.async, LDSM + LDSM.T ----------------
// EPI2 == false : g_h[p,:] = relu(g_xg[p,:] @ W1[g] + b1[g])   bf16 out
// EPI2 == true  : g_pre[t,:] = x[t,:] + alpha[g]*(g_h[p,:] @ W2[g] + b2[g]),
//                 per-token sumsq atomics, and the LAST CTA per (g,mtile)
//                 normalizes its 64 rows into `gout` (fused normalize).
template<int K, bool EPI2>
__global__ void __launch_bounds__(256, 3) gemm_kernel(
    const float* __restrict__ bias,        // [E][NTOT] fp32
    const float* __restrict__ x,
    float* __restrict__ gout)              // final output (EPI2 only)
{
    constexpr int BM = 64, BN = 128, BK = 32;
    constexpr int LDA = 40;
    constexpr int LDB = 136;
    constexpr int NTOT = EPI2 ? DDIM : HDIM;
    constexpr int NIT  = K / BK;
    constexpr int A_ELEMS = BM * LDA;                 // 2560
    constexpr int STAGE_ELEMS = A_ELEMS + BK * LDB;   // 6912
    constexpr int STAGE_BYTES = STAGE_ELEMS * 2;      // 13824
    constexpr int B_BYTE_OFF  = A_ELEMS * 2;          // 5120

    extern __shared__ __align__(16) unsigned char smem_raw[];
    __shared__ int s_last;
    __nv_bfloat16* smem = reinterpret_cast<__nv_bfloat16*>(smem_raw);
    uint32_t sbase = (uint32_t)__cvta_generic_to_shared(smem_raw);

    const __nv_bfloat16* A  = EPI2 ? g_h   : g_xg;
    const __nv_bfloat16* Bw = EPI2 ? g_W2b : g_W1b;   // device-side symbol access

    int g     = blockIdx.z;
    int start = g_gstart[g];
    int cnt   = g_gstart[g + 1] - start;
    int m0    = blockIdx.x * BM;
    if (m0 >= cnt) return;
    int n0 = blockIdx.y * BN;
    const __nv_bfloat16* Bg = Bw + (size_t)g * K * NTOT;
    const __nv_bfloat16* Ag = A + (size_t)start * K;

    int tid  = threadIdx.x;
    int warp = tid >> 5, lane = tid & 31;
    int wm = (warp & 1) * 32;       // 2 warps over M
    int wn = (warp >> 1) * 32;      // 4 warps over N
    int lrow = lane >> 2;
    int lcol = (lane & 3) * 2;

    int l15 = lane & 15, lhi = lane >> 4;
    uint32_t aOff[2];
    #pragma unroll
    for (int mi = 0; mi < 2; mi++)
        aOff[mi] = (uint32_t)(((wm + mi * 16 + l15) * LDA + lhi * 8) * 2);
    uint32_t bOff[2];
    #pragma unroll
    for (int j = 0; j < 2; j++)
        bOff[j] = (uint32_t)(B_BYTE_OFF + (l15 * LDB + wn + j * 16 + lhi * 8) * 2);

    auto load_stage = [&](int s, int k0) {
        __nv_bfloat16* As = smem + s * STAGE_ELEMS;
        __nv_bfloat16* Bs = As + A_ELEMS;
        {
            int r = tid >> 2, v = tid & 3;
            bool p = (m0 + r) < cnt;
            int rr = p ? (m0 + r) : 0;
            cp_async16(&As[r * LDA + v * 8], Ag + (size_t)rr * K + k0 + v * 8, p);
        }
        #pragma unroll
        for (int i = 0; i < 2; i++) {
            int c = tid + i * 256;
            int r = c >> 4, v = c & 15;
            cp_async16(&Bs[r * LDB + v * 8],
                       Bg + (size_t)(k0 + r) * NTOT + n0 + v * 8, true);
        }
    };

    float acc[2][4][4];
    #pragma unroll
    for (int mi = 0; mi < 2; mi++)
        #pragma unroll
        for (int ni = 0; ni < 4; ni++)
            #pragma unroll
            for (int qq = 0; qq < 4; qq++) acc[mi][ni][qq] = 0.f;

    load_stage(0, 0);
    CP_COMMIT();
    load_stage(1, BK);
    CP_COMMIT();

    for (int it = 0; it < NIT; it++) {
        CP_WAIT1();
        __syncthreads();

        if (it + 2 < NIT) load_stage((it + 2) % 3, (it + 2) * BK);
        CP_COMMIT();

        uint32_t stg = sbase + (uint32_t)((it % 3) * STAGE_BYTES);
        #pragma unroll
        for (int kk = 0; kk < BK; kk += 16) {
            uint32_t af[2][4], bq[2][4];
            #pragma unroll
            for (int mi = 0; mi < 2; mi++)
                ldsm_x4(af[mi][0], af[mi][1], af[mi][2], af[mi][3],
                        stg + aOff[mi] + kk * 2);
            #pragma unroll
            for (int j = 0; j < 2; j++)
                ldsm_x4_t(bq[j][0], bq[j][1], bq[j][2], bq[j][3],
                          stg + bOff[j] + kk * (LDB * 2));
            #pragma unroll
            for (int mi = 0; mi < 2; mi++)
                #pragma unroll
                for (int ni = 0; ni < 4; ni++)
                    mma16816(acc[mi][ni], af[mi], &bq[ni >> 1][(ni & 1) * 2]);
        }
    }

    // ---- epilogue ----
    float alpha = EPI2 ? g_alpha[g] : 0.f;
    const float* bg = bias + (size_t)g * NTOT;
    #pragma unroll
    for (int mi = 0; mi < 2; mi++) {
        #pragma unroll
        for (int half = 0; half < 2; half++) {
            int rloc = wm + mi * 16 + lrow + half * 8;
            int grow = m0 + rloc;
            bool valid = grow < cnt;
            if (!EPI2) {
                if (!valid) continue;
                #pragma unroll
                for (int ni = 0; ni < 4; ni++) {
                    int c = n0 + wn + ni * 8 + lcol;
                    float v0 = fmaxf(acc[mi][ni][half * 2 + 0] + bg[c], 0.f);
                    float v1 = fmaxf(acc[mi][ni][half * 2 + 1] + bg[c + 1], 0.f);
                    __nv_bfloat162 pk = __floats2bfloat162_rn(v0, v1);
                    *reinterpret_cast<__nv_bfloat162*>(
                        &g_h[(size_t)(start + grow) * HDIM + c]) = pk;
                }
            } else {
                int t = valid ? g_perm[start + grow] : 0;
                float s = 0.f;
                #pragma unroll
                for (int ni = 0; ni < 4; ni++) {
                    int c = n0 + wn + ni * 8 + lcol;
                    float v0 = acc[mi][ni][half * 2 + 0] + bg[c];
                    float v1 = acc[mi][ni][half * 2 + 1] + bg[c + 1];
                    if (valid) {
                        float2 xv = *reinterpret_cast<const float2*>(x + (size_t)t * DDIM + c);
                        float2 o;
                        o.x = xv.x + alpha * v0;
                        o.y = xv.y + alpha * v1;
                        *reinterpret_cast<float2*>(&g_pre[(size_t)t * DDIM + c]) = o;
                        s += o.x * o.x + o.y * o.y;
                    }
                }
                // reduce over the 4 lanes (lcol groups) covering this row
                s += __shfl_xor_sync(0xffffffffu, s, 1);
                s += __shfl_xor_sync(0xffffffffu, s, 2);
                if (valid && (lane & 3) == 0) atomicAdd(&g_sumsq[t], s);
            }
        }
    }

    if (EPI2) {
        __threadfence();
        __syncthreads();
        if (tid == 0) s_last = atomicAdd(&g_cnt[g * (NTOK / 64) + blockIdx.x], 1);
        __syncthreads();
        if (s_last == (NTOT / BN) - 1) {           // last of 6 CTAs for this (g, mtile)
            #pragma unroll
            for (int j = 0; j < 8; j++) {
                int grow = m0 + warp * 8 + j;
                if (grow >= cnt) continue;
                int t = g_perm[start + grow];
                float inv = 1.f / fmaxf(sqrtf(g_sumsq[t]), 1e-12f);
                const float4* pr = reinterpret_cast<const float4*>(g_pre + (size_t)t * DDIM);
                float4* po = reinterpret_cast<float4*>(gout + (size_t)t * DDIM);
                #pragma unroll
                for (int q = 0; q < 6; q++) {
                    float4 v = pr[lane + q * 32];
                    v.x *= inv; v.y *= inv; v.z *= inv; v.w *= inv;
                    po[lane + q * 32] = v;
                }
            }
        }
    }
}

// ---------------- launch: forked-stream graph ----------------
extern "C" void kernel_launch(void* const* d_in, const int* in_sizes, int n_in,
                              void* d_out, int out_size) {
    const float* x         = (const float*)d_in[0];
    const int*   ids       = (const int*)d_in[1];
    const float* W1        = (const float*)d_in[2];
    const float* b1        = (const float*)d_in[3];
    const float* W2        = (const float*)d_in[4];
    const float* b2        = (const float*)d_in[5];
    const float* raw_alpha = (const float*)d_in[6];
    const int*   e2g       = (const int*)d_in[7];
    int T = in_sizes[7];

    static cudaStream_t s1 = nullptr, s2 = nullptr;
    static cudaEvent_t  eRoot = nullptr, eW1 = nullptr, eW2 = nullptr;
    static bool smem_set = false;
    if (!s1) {
        cudaStreamCreateWithFlags(&s1, cudaStreamNonBlocking);
        cudaStreamCreateWithFlags(&s2, cudaStreamNonBlocking);
        cudaEventCreateWithFlags(&eRoot, cudaEventDisableTiming);
        cudaEventCreateWithFlags(&eW1,   cudaEventDisableTiming);
        cudaEventCreateWithFlags(&eW2,   cudaEventDisableTiming);
    }
    constexpr int SMEM_GEMM = (64 * 40 + 32 * 136) * 2 * 3;   // 41472 B
    if (!smem_set) {
        cudaFuncSetAttribute(gemm_kernel<DDIM, false>,
                             cudaFuncAttributeMaxDynamicSharedMemorySize, SMEM_GEMM);
        cudaFuncSetAttribute(gemm_kernel<HDIM, true>,
                             cudaFuncAttributeMaxDynamicSharedMemorySize, SMEM_GEMM);
        smem_set = true;
    }

    // fork
    cudaEventRecord(eRoot, 0);
    cudaStreamWaitEvent(s1, eRoot, 0);
    cudaStreamWaitEvent(s2, eRoot, 0);

    // side branches: weight converts
    convert_kernel<<<1728, 256, 0, s1>>>(W1, 0);
    cudaEventRecord(eW1, s1);
    convert_kernel<<<1728, 256, 0, s2>>>(W2, 1);
    cudaEventRecord(eW2, s2);

    // main branch
    prep_kernel<<<1, 256>>>(ids, e2g, raw_alpha, T);
    gather_kernel<<<1536, 256>>>(x);

    cudaStreamWaitEvent(0, eW1, 0);
    gemm_kernel<DDIM, false><<<dim3(NTOK / 64, HDIM / 128, NE), 256, SMEM_GEMM>>>(b1, x, nullptr);

    cudaStreamWaitEvent(0, eW2, 0);
    gemm_kernel<HDIM, true ><<<dim3(NTOK / 64, DDIM / 128, NE), 256, SMEM_GEMM>>>(b2, x, (float*)d_out);
}

// round 13
// speedup vs baseline: 1.1603x; 1.1603x over previous
#include <cuda_runtime.h>
#include <cuda_bf16.h>
#include <cstdint>
#include <math.h>

#define NTOK 4096
#define DDIM 768
#define HDIM 1536
#define NE   6
#define NCTA 444   // 148 SMs x 3 CTAs/SM

// ---------------- device scratch ----------------
__device__ int   g_perm[NTOK];
__device__ int   g_gstart[NE + 1];
__device__ float g_alpha[NE];
__device__ __nv_bfloat16 g_xg[(size_t)NTOK * DDIM];          // gathered x, perm order (bf16)
__device__ __nv_bfloat16 g_h [(size_t)NTOK * HDIM];          // relu hidden, perm order
__device__ __nv_bfloat16 g_W1b[(size_t)NE * DDIM * HDIM];    // bf16 W1, native [e][d][h]
__device__ __nv_bfloat16 g_W2b[(size_t)NE * HDIM * DDIM];    // bf16 W2, native [e][h][d]
__device__ float g_pre[(size_t)NTOK * DDIM];                 // x + alpha*r, token order

// ---------------- asm helpers ----------------
__device__ __forceinline__ void cp_async16(void* smem, const void* g, bool pred) {
    uint32_t s = (uint32_t)__cvta_generic_to_shared(smem);
    int sz = pred ? 16 : 0;   // src-size 0 -> 16B zero-fill
    asm volatile("cp.async.cg.shared.global [%0], [%1], 16, %2;\n" :: "r"(s), "l"(g), "r"(sz));
}
#define CP_COMMIT() asm volatile("cp.async.commit_group;\n" ::: "memory")
#define CP_WAIT1()  asm volatile("cp.async.wait_group 1;\n" ::: "memory")

__device__ __forceinline__ void ldsm_x4(uint32_t& r0, uint32_t& r1, uint32_t& r2, uint32_t& r3,
                                        uint32_t addr) {
    asm volatile("ldmatrix.sync.aligned.m8n8.x4.shared.b16 {%0,%1,%2,%3}, [%4];"
                 : "=r"(r0), "=r"(r1), "=r"(r2), "=r"(r3) : "r"(addr));
}
__device__ __forceinline__ void ldsm_x4_t(uint32_t& r0, uint32_t& r1, uint32_t& r2, uint32_t& r3,
                                          uint32_t addr) {
    asm volatile("ldmatrix.sync.aligned.m8n8.x4.trans.shared.b16 {%0,%1,%2,%3}, [%4];"
                 : "=r"(r0), "=r"(r1), "=r"(r2), "=r"(r3) : "r"(addr));
}

__device__ __forceinline__ void mma16816(float* c, const uint32_t* a, const uint32_t* b) {
    asm volatile(
        "mma.sync.aligned.m16n8k16.row.col.f32.bf16.bf16.f32 "
        "{%0,%1,%2,%3}, {%4,%5,%6,%7}, {%8,%9}, {%0,%1,%2,%3};\n"
        : "+f"(c[0]), "+f"(c[1]), "+f"(c[2]), "+f"(c[3])
        : "r"(a[0]), "r"(a[1]), "r"(a[2]), "r"(a[3]), "r"(b[0]), "r"(b[1]));
}

// ---------------- prep: sort tokens by group ----------------
__global__ void prep_kernel(const int* __restrict__ ids,
                            const int* __restrict__ e2g,
                            const float* __restrict__ raw_alpha,
                            int T) {
    __shared__ int cnt[NE];
    __shared__ int cur[NE];
    __shared__ unsigned char gid_s[NTOK];
    int tid = threadIdx.x;
    if (tid < NE) cnt[tid] = 0;
    __syncthreads();
    for (int i = tid; i < NTOK; i += blockDim.x) {
        int ty = ids[i];
        ty = ty < 0 ? 0 : (ty > T - 1 ? T - 1 : ty);
        int gd = e2g[ty];
        gid_s[i] = (unsigned char)gd;
        atomicAdd(&cnt[gd], 1);
    }
    __syncthreads();
    if (tid == 0) {
        int acc = 0;
        for (int e = 0; e < NE; e++) { g_gstart[e] = acc; cur[e] = acc; acc += cnt[e]; }
        g_gstart[NE] = acc;
    }
    __syncthreads();
    for (int i = tid; i < NTOK; i += blockDim.x) {
        int pos = atomicAdd(&cur[gid_s[i]], 1);
        g_perm[pos] = i;
    }
    if (tid < NE) g_alpha[tid] = 0.05f / (1.0f + expf(-raw_alpha[tid]));
}

// ---------------- streaming fp32 -> bf16 weight convert (16 elems/thread) ----------------
__global__ void convert_kernel(const float* __restrict__ in, int which) {
    __nv_bfloat16* out = which ? g_W2b : g_W1b;
    size_t i0 = ((size_t)blockIdx.x * 256 + threadIdx.x) * 16;
    #pragma unroll
    for (int h = 0; h < 2; h++) {
        float4 a = *reinterpret_cast<const float4*>(in + i0 + h * 8);
        float4 b = *reinterpret_cast<const float4*>(in + i0 + h * 8 + 4);
        __nv_bfloat162 h0 = __floats2bfloat162_rn(a.x, a.y);
        __nv_bfloat162 h1 = __floats2bfloat162_rn(a.z, a.w);
        __nv_bfloat162 h2 = __floats2bfloat162_rn(b.x, b.y);
        __nv_bfloat162 h3 = __floats2bfloat162_rn(b.z, b.w);
        uint4 o;
        o.x = *reinterpret_cast<uint32_t*>(&h0);
        o.y = *reinterpret_cast<uint32_t*>(&h1);
        o.z = *reinterpret_cast<uint32_t*>(&h2);
        o.w = *reinterpret_cast<uint32_t*>(&h3);
        *reinterpret_cast<uint4*>(out + i0 + h * 8) = o;
    }
}

// ---------------- gather: one float4 per thread ----------------
__global__ void gather_kernel(const float* __restrict__ x) {
    int idx = blockIdx.x * 256 + threadIdx.x;
    int p = idx / 192, j = idx % 192;
    int t = g_perm[p];
    float4 v = *(reinterpret_cast<const float4*>(x + (size_t)t * DDIM) + j);
    __nv_bfloat162 h0 = __floats2bfloat162_rn(v.x, v.y);
    __nv_bfloat162 h1 = __floats2bfloat162_rn(v.z, v.w);
    uint2 o;
    o.x = *reinterpret_cast<uint32_t*>(&h0);
    o.y = *reinterpret_cast<uint32_t*>(&h1);
    *(reinterpret_cast<uint2*>(g_xg + (size_t)p * DDIM) + j) = o;
}

// ---------------- persistent grouped GEMM: BM=64, 3-stage cp.async, tile loop ----------------
// EPI2 == false : g_h[p,:] = relu(g_xg[p,:] @ W1[g] + b1[g])   bf16 out
// EPI2 == true  : g_pre[t,:] = x[t,:] + alpha[g] * (g_h[p,:] @ W2[g] + b2[g])
template<int K, bool EPI2>
__global__ void __launch_bounds__(256, 3) gemm_kernel(
    const float* __restrict__ bias,        // [E][NTOT] fp32
    const float* __restrict__ x)
{
    constexpr int BM = 64, BN = 128, BK = 32;
    constexpr int LDA = 40;
    constexpr int LDB = 136;
    constexpr int NTOT = EPI2 ? DDIM : HDIM;
    constexpr int NIT  = K / BK;            // 24 or 48 (divisible by 3 -> safe stage reuse)
    constexpr int NT   = NTOT / BN;         // n-tiles: 6 or 12
    constexpr int PER_X = NE * NT;          // logical tiles per m-tile index
    constexpr int TOTAL = (NTOK / BM) * PER_X;
    constexpr int A_ELEMS = BM * LDA;                 // 2560
    constexpr int STAGE_ELEMS = A_ELEMS + BK * LDB;   // 6912
    constexpr int STAGE_BYTES = STAGE_ELEMS * 2;      // 13824
    constexpr int B_BYTE_OFF  = A_ELEMS * 2;          // 5120

    extern __shared__ __align__(16) unsigned char smem_raw[];
    __nv_bfloat16* smem = reinterpret_cast<__nv_bfloat16*>(smem_raw);
    uint32_t sbase = (uint32_t)__cvta_generic_to_shared(smem_raw);

    const __nv_bfloat16* A  = EPI2 ? g_h   : g_xg;
    const __nv_bfloat16* Bw = EPI2 ? g_W2b : g_W1b;

    int tid  = threadIdx.x;
    int warp = tid >> 5, lane = tid & 31;
    int wm = (warp & 1) * 32;       // 2 warps over M
    int wn = (warp >> 1) * 32;      // 4 warps over N
    int lrow = lane >> 2;
    int lcol = (lane & 3) * 2;

    int l15 = lane & 15, lhi = lane >> 4;
    uint32_t aOff[2];
    #pragma unroll
    for (int mi = 0; mi < 2; mi++)
        aOff[mi] = (uint32_t)(((wm + mi * 16 + l15) * LDA + lhi * 8) * 2);
    uint32_t bOff[2];
    #pragma unroll
    for (int j = 0; j < 2; j++)
        bOff[j] = (uint32_t)(B_BYTE_OFF + (l15 * LDB + wn + j * 16 + lhi * 8) * 2);

    for (int idx = blockIdx.x; idx < TOTAL; idx += NCTA) {
        int mx  = idx / PER_X;
        int rem = idx - mx * PER_X;
        int g   = rem / NT;
        int ny  = rem - g * NT;

        int start = g_gstart[g];
        int cnt   = g_gstart[g + 1] - start;
        int m0    = mx * BM;
        if (m0 >= cnt) continue;
        int n0 = ny * BN;
        const __nv_bfloat16* Bg = Bw + (size_t)g * K * NTOT;
        const __nv_bfloat16* Ag = A + (size_t)start * K;

        auto load_stage = [&](int s, int k0) {
            __nv_bfloat16* As = smem + s * STAGE_ELEMS;
            __nv_bfloat16* Bs = As + A_ELEMS;
            {
                int r = tid >> 2, v = tid & 3;
                bool p = (m0 + r) < cnt;
                int rr = p ? (m0 + r) : 0;
                cp_async16(&As[r * LDA + v * 8], Ag + (size_t)rr * K + k0 + v * 8, p);
            }
            #pragma unroll
            for (int i = 0; i < 2; i++) {
                int c = tid + i * 256;
                int r = c >> 4, v = c & 15;
                cp_async16(&Bs[r * LDB + v * 8],
                           Bg + (size_t)(k0 + r) * NTOT + n0 + v * 8, true);
            }
        };

        float acc[2][4][4];
        #pragma unroll
        for (int mi = 0; mi < 2; mi++)
            #pragma unroll
            for (int ni = 0; ni < 4; ni++)
                #pragma unroll
                for (int qq = 0; qq < 4; qq++) acc[mi][ni][qq] = 0.f;

        // all warps must be done with the previous tile's smem before refilling
        __syncthreads();

        load_stage(0, 0);
        CP_COMMIT();
        load_stage(1, BK);
        CP_COMMIT();

        for (int it = 0; it < NIT; it++) {
            CP_WAIT1();
            __syncthreads();

            if (it + 2 < NIT) load_stage((it + 2) % 3, (it + 2) * BK);
            CP_COMMIT();

            uint32_t stg = sbase + (uint32_t)((it % 3) * STAGE_BYTES);
            #pragma unroll
            for (int kk = 0; kk < BK; kk += 16) {
                uint32_t af[2][4], bq[2][4];
                #pragma unroll
                for (int mi = 0; mi < 2; mi++)
                    ldsm_x4(af[mi][0], af[mi][1], af[mi][2], af[mi][3],
                            stg + aOff[mi] + kk * 2);
                #pragma unroll
                for (int j = 0; j < 2; j++)
                    ldsm_x4_t(bq[j][0], bq[j][1], bq[j][2], bq[j][3],
                              stg + bOff[j] + kk * (LDB * 2));
                #pragma unroll
                for (int mi = 0; mi < 2; mi++)
                    #pragma unroll
                    for (int ni = 0; ni < 4; ni++)
                        mma16816(acc[mi][ni], af[mi], &bq[ni >> 1][(ni & 1) * 2]);
            }
        }

        // ---- epilogue ----
        float alpha = EPI2 ? g_alpha[g] : 0.f;
        const float* bg = bias + (size_t)g * NTOT;
        #pragma unroll
        for (int mi = 0; mi < 2; mi++) {
            #pragma unroll
            for (int half = 0; half < 2; half++) {
                int rloc = wm + mi * 16 + lrow + half * 8;
                int grow = m0 + rloc;
                if (grow >= cnt) continue;
                #pragma unroll
                for (int ni = 0; ni < 4; ni++) {
                    int c = n0 + wn + ni * 8 + lcol;
                    float v0 = acc[mi][ni][half * 2 + 0] + bg[c];
                    float v1 = acc[mi][ni][half * 2 + 1] + bg[c + 1];
                    if (!EPI2) {
                        v0 = fmaxf(v0, 0.f);
                        v1 = fmaxf(v1, 0.f);
                        __nv_bfloat162 pk = __floats2bfloat162_rn(v0, v1);
                        *reinterpret_cast<__nv_bfloat162*>(
                            &g_h[(size_t)(start + grow) * HDIM + c]) = pk;
                    } else {
                        int t = g_perm[start + grow];
                        float2 xv = *reinterpret_cast<const float2*>(x + (size_t)t * DDIM + c);
                        float2 o;
                        o.x = xv.x + alpha * v0;
                        o.y = xv.y + alpha * v1;
                        *reinterpret_cast<float2*>(&g_pre[(size_t)t * DDIM + c]) = o;
                    }
                }
            }
        }
    }
}

// ---------------- normalize ----------------
__global__ void normalize_kernel(float* __restrict__ out) {
    int t = blockIdx.x;
    const float4* pr = reinterpret_cast<const float4*>(g_pre) + (size_t)t * 192;
    float4 v = pr[threadIdx.x];
    float s = v.x * v.x + v.y * v.y + v.z * v.z + v.w * v.w;
    #pragma unroll
    for (int o = 16; o > 0; o >>= 1) s += __shfl_xor_sync(0xffffffffu, s, o);
    __shared__ float red[6];
    int warp = threadIdx.x >> 5, lane = threadIdx.x & 31;
    if (lane == 0) red[warp] = s;
    __syncthreads();
    if (threadIdx.x == 0) {
        float z = 0.f;
        #pragma unroll
        for (int i = 0; i < 6; i++) z += red[i];
        red[0] = 1.f / fmaxf(sqrtf(z), 1e-12f);
    }
    __syncthreads();
    float inv = red[0];
    float4 o;
    o.x = v.x * inv; o.y = v.y * inv; o.z = v.z * inv; o.w = v.w * inv;
    reinterpret_cast<float4*>(out)[(size_t)t * 192 + threadIdx.x] = o;
}

// ---------------- launch: forked-stream graph ----------------
extern "C" void kernel_launch(void* const* d_in, const int* in_sizes, int n_in,
                              void* d_out, int out_size) {
    const float* x         = (const float*)d_in[0];
    const int*   ids       = (const int*)d_in[1];
    const float* W1        = (const float*)d_in[2];
    const float* b1        = (const float*)d_in[3];
    const float* W2        = (const float*)d_in[4];
    const float* b2        = (const float*)d_in[5];
    const float* raw_alpha = (const float*)d_in[6];
    const int*   e2g       = (const int*)d_in[7];
    int T = in_sizes[7];

    static cudaStream_t s1 = nullptr, s2 = nullptr;
    static cudaEvent_t  eRoot = nullptr, eW1 = nullptr, eW2 = nullptr;
    static bool smem_set = false;
    if (!s1) {
        cudaStreamCreateWithFlags(&s1, cudaStreamNonBlocking);
        cudaStreamCreateWithFlags(&s2, cudaStreamNonBlocking);
        cudaEventCreateWithFlags(&eRoot, cudaEventDisableTiming);
        cudaEventCreateWithFlags(&eW1,   cudaEventDisableTiming);
        cudaEventCreateWithFlags(&eW2,   cudaEventDisableTiming);
    }
    constexpr int SMEM_GEMM = (64 * 40 + 32 * 136) * 2 * 3;   // 41472 B
    if (!smem_set) {
        cudaFuncSetAttribute(gemm_kernel<DDIM, false>,
                             cudaFuncAttributeMaxDynamicSharedMemorySize, SMEM_GEMM);
        cudaFuncSetAttribute(gemm_kernel<HDIM, true>,
                             cudaFuncAttributeMaxDynamicSharedMemorySize, SMEM_GEMM);
        smem_set = true;
    }

    // fork
    cudaEventRecord(eRoot, 0);
    cudaStreamWaitEvent(s1, eRoot, 0);
    cudaStreamWaitEvent(s2, eRoot, 0);

    // side branches: weight converts
    convert_kernel<<<1728, 256, 0, s1>>>(W1, 0);
    cudaEventRecord(eW1, s1);
    convert_kernel<<<1728, 256, 0, s2>>>(W2, 1);
    cudaEventRecord(eW2, s2);

    // main branch
    prep_kernel<<<1, 256>>>(ids, e2g, raw_alpha, T);
    gather_kernel<<<3072, 256>>>(x);

    cudaStreamWaitEvent(0, eW1, 0);
    gemm_kernel<DDIM, false><<<NCTA, 256, SMEM_GEMM>>>(b1, x);

    cudaStreamWaitEvent(0, eW2, 0);
    gemm_kernel<HDIM, true ><<<NCTA, 256, SMEM_GEMM>>>(b2, x);

    normalize_kernel<<<NTOK, 192>>>((float*)d_out);
}